// round 6
// baseline (speedup 1.0000x reference)
#include <cuda_runtime.h>

#define NN 50000
#define EE 800000
#define HH 128
#define NEGS 0.2f
#define EPSB 1e-5f

// ------------------------- device scratch ----------------------------------
__device__ float g_buf0[NN * HH];
__device__ float g_buf1[NN * HH];
__device__ float g_hp[NN * HH];
__device__ float g_s[NN * 4];
__device__ float g_d[NN * 4];
__device__ float g_ew[EE * 4];
__device__ float g_Wt[3 * HH * HH];
__device__ int   g_deg[NN];
__device__ int   g_cur[NN];
__device__ int   g_off[NN + 1];
__device__ int   g_csrc[EE];
__device__ int   g_cdst[EE];
__device__ float g_part[256 * HH];
__device__ float g_part2[256 * HH];
__device__ float g_scale[HH];
__device__ float g_shift[HH];

__device__ __forceinline__ float lrelu(float v) { return v > 0.f ? v : NEGS * v; }

// packed f32x2 helpers (FFMA2 — only reachable via PTX)
__device__ __forceinline__ unsigned long long pack2(float lo, float hi) {
    unsigned long long r;
    asm("mov.b64 %0, {%1, %2};" : "=l"(r) : "f"(lo), "f"(hi));
    return r;
}
__device__ __forceinline__ void fma2(unsigned long long& d, unsigned long long a,
                                     unsigned long long b) {
    asm("fma.rn.f32x2 %0, %1, %2, %0;" : "+l"(d) : "l"(a), "l"(b));
}
__device__ __forceinline__ float2 up2(unsigned long long v) {
    float2 r;
    asm("mov.b64 {%0, %1}, %2;" : "=f"(r.x), "=f"(r.y) : "l"(v));
    return r;
}

// ------------------------- CSR build ----------------------------------------
__global__ void k_zero2(int* __restrict__ a, int* __restrict__ b, int n) {
    int i = blockIdx.x * blockDim.x + threadIdx.x;
    if (i < n) { a[i] = 0; b[i] = 0; }
}

__global__ void k_hist(const int* __restrict__ dst, int* __restrict__ deg) {
    int e = blockIdx.x * blockDim.x + threadIdx.x;
    if (e < EE) atomicAdd(&deg[dst[e]], 1);
}

__global__ void k_scan(const int* __restrict__ deg, int* __restrict__ off) {
    __shared__ int ssum[1024];
    int t = threadIdx.x;
    const int CH = (NN + 1023) / 1024;
    int beg = t * CH;
    int end = beg + CH; if (end > NN) end = NN;
    int s = 0;
    for (int i = beg; i < end; i++) s += deg[i];
    ssum[t] = s;
    __syncthreads();
    for (int o = 1; o < 1024; o <<= 1) {
        int v = 0;
        if (t >= o) v = ssum[t - o];
        __syncthreads();
        if (t >= o) ssum[t] += v;
        __syncthreads();
    }
    int run = (t > 0) ? ssum[t - 1] : 0;
    for (int i = beg; i < end; i++) { off[i] = run; run += deg[i]; }
    if (t == 1023) off[NN] = ssum[1023];
}

__global__ void k_fill(const int* __restrict__ src, const int* __restrict__ dst,
                       int* __restrict__ cur, const int* __restrict__ off,
                       int* __restrict__ csrc, int* __restrict__ cdst) {
    int e = blockIdx.x * blockDim.x + threadIdx.x;
    if (e < EE) {
        int d = dst[e];
        int p = off[d] + atomicAdd(&cur[d], 1);
        csrc[p] = src[e];
        cdst[p] = d;
    }
}

// ------------------------- weight transpose: Wt[k][c] = W[c][k] -------------
__global__ void k_t128(const float* __restrict__ W, float* __restrict__ Wt) {
    int idx = blockIdx.x * blockDim.x + threadIdx.x;
    if (idx < 128 * 128) {
        int c = idx >> 7, k = idx & 127;
        Wt[k * 128 + c] = W[idx];
    }
}

// ------------------------- input layer --------------------------------------
__global__ void k_input(const float* __restrict__ x, const float* __restrict__ Win,
                        const float* __restrict__ bin, float* __restrict__ out) {
    int n = blockIdx.x * 2 + (threadIdx.x >> 7);
    int c = threadIdx.x & 127;
    if (n >= NN) return;
    float a = bin[c];
#pragma unroll
    for (int k = 0; k < 5; k++) a = fmaf(x[n * 5 + k], Win[c * 5 + k], a);
    out[n * 128 + c] = fmaxf(a, 0.f);
}

// ------------------------- fused BN+relu + GEMM + attn coefficients ---------
// Block = 128 rows x 64 cols (blockIdx.y = column half). 256 threads.
// Thread (t): rows (t>>4)*8 .. +7, cols c0 + (t&15)*4 .. +3.
// FFMA2 packed along k: A in natural [row][k] layout (k-pairs free via u64
// reinterpret), W k-pairs built with mov.b64 from Wt[k][c] tiles.
template <int HEADS>
__global__ void __launch_bounds__(256, 2)
k_gemm(const float* __restrict__ in, const float* __restrict__ Wt,
       const float* __restrict__ as_, const float* __restrict__ ad_,
       const float* __restrict__ scale, const float* __restrict__ shift,
       int useBN, float* __restrict__ hp,
       float* __restrict__ sarr, float* __restrict__ darr) {
    extern __shared__ float smf[];
    float* Asm = smf;              // [128 rows][132]  Asm[row][k]
    float* Wsm = smf + 128 * 132;  // [128 k][68]      Wsm[k][c]
    int t = threadIdx.x;
    int n0 = blockIdx.x * 128;
    int c0 = blockIdx.y * 64;

    // ---- A fill: natural layout, fully coalesced, conflict-free ----
    {
        int kc = (t & 31) * 4;
        int row0 = t >> 5;
        float4 sc4 = make_float4(1.f, 1.f, 1.f, 1.f);
        float4 sh4 = make_float4(0.f, 0.f, 0.f, 0.f);
        if (useBN) {
            sc4 = *(const float4*)(scale + kc);
            sh4 = *(const float4*)(shift + kc);
        }
#pragma unroll
        for (int i = 0; i < 16; i++) {
            int row = row0 + i * 8;
            int n = n0 + row;
            float4 v = make_float4(0.f, 0.f, 0.f, 0.f);
            if (n < NN) {
                v = *(const float4*)(in + n * 128 + kc);
                if (useBN) {
                    v.x = fmaxf(fmaf(v.x, sc4.x, sh4.x), 0.f);
                    v.y = fmaxf(fmaf(v.y, sc4.y, sh4.y), 0.f);
                    v.z = fmaxf(fmaf(v.z, sc4.z, sh4.z), 0.f);
                    v.w = fmaxf(fmaf(v.w, sc4.w, sh4.w), 0.f);
                }
            }
            *(float4*)(Asm + row * 132 + kc) = v;
        }
    }
    // ---- W fill: copy from pre-transposed Wt ----
#pragma unroll
    for (int i = 0; i < 8; i++) {
        int idx4 = t + i * 256;
        int k = idx4 >> 4, cc = (idx4 & 15) * 4;
        float4 v = *(const float4*)(Wt + k * 128 + c0 + cc);
        *(float4*)(Wsm + k * 68 + cc) = v;
    }
    __syncthreads();

    int gr = t >> 4;          // 0..15
    int gc = t & 15;          // 0..15
    int rbase = gr * 8;
    int cbase = gc * 4;
    const float* ap = Asm + rbase * 132;
    const float* wp = Wsm + cbase;

    unsigned long long acc[8][4];
#pragma unroll
    for (int r = 0; r < 8; r++)
#pragma unroll
        for (int c = 0; c < 4; c++) acc[r][c] = 0ull;

    for (int k = 0; k < 128; k += 4) {
        // W: 4 per-k float4 rows -> 8 k-paired u64 (one lo/hi pair per col)
        float4 w0 = *(const float4*)(wp + (k + 0) * 68);
        float4 w1 = *(const float4*)(wp + (k + 1) * 68);
        float4 w2 = *(const float4*)(wp + (k + 2) * 68);
        float4 w3 = *(const float4*)(wp + (k + 3) * 68);
        unsigned long long wl[4], wh[4];
        wl[0] = pack2(w0.x, w1.x); wl[1] = pack2(w0.y, w1.y);
        wl[2] = pack2(w0.z, w1.z); wl[3] = pack2(w0.w, w1.w);
        wh[0] = pack2(w2.x, w3.x); wh[1] = pack2(w2.y, w3.y);
        wh[2] = pack2(w2.z, w3.z); wh[3] = pack2(w2.w, w3.w);
#pragma unroll
        for (int r = 0; r < 8; r++) {
            ulonglong2 ar = *(const ulonglong2*)(ap + r * 132 + k);
#pragma unroll
            for (int c = 0; c < 4; c++) {
                fma2(acc[r][c], ar.x, wl[c]);
                fma2(acc[r][c], ar.y, wh[c]);
            }
        }
    }

    // reduce k-pairs
    float accf[8][4];
#pragma unroll
    for (int r = 0; r < 8; r++)
#pragma unroll
        for (int c = 0; c < 4; c++) {
            float2 f = up2(acc[r][c]);
            accf[r][c] = f.x + f.y;
        }

    // store hp
#pragma unroll
    for (int rr = 0; rr < 8; rr++) {
        int n = n0 + rbase + rr;
        if (n < NN)
            *(float4*)&hp[n * 128 + c0 + cbase] =
                make_float4(accf[rr][0], accf[rr][1], accf[rr][2], accf[rr][3]);
    }

    // attention coefficients
    float asv[4], adv[4];
#pragma unroll
    for (int j = 0; j < 4; j++) {
        asv[j] = as_[c0 + cbase + j];
        adv[j] = ad_[c0 + cbase + j];
    }
    int l = t & 31;
#pragma unroll
    for (int rr = 0; rr < 8; rr++) {
        float ps = 0.f, pd = 0.f;
#pragma unroll
        for (int j = 0; j < 4; j++) {
            ps = fmaf(accf[rr][j], asv[j], ps);
            pd = fmaf(accf[rr][j], adv[j], pd);
        }
        if (HEADS == 4) {
            ps += __shfl_xor_sync(0xffffffffu, ps, 1);
            ps += __shfl_xor_sync(0xffffffffu, ps, 2);
            ps += __shfl_xor_sync(0xffffffffu, ps, 4);
            pd += __shfl_xor_sync(0xffffffffu, pd, 1);
            pd += __shfl_xor_sync(0xffffffffu, pd, 2);
            pd += __shfl_xor_sync(0xffffffffu, pd, 4);
            if ((l & 7) == 0) {
                int n = n0 + rbase + rr;
                if (n < NN) {
                    int h = blockIdx.y * 2 + ((l >> 3) & 1);
                    sarr[n * 4 + h] = ps;
                    darr[n * 4 + h] = pd;
                }
            }
        } else {
            ps += __shfl_xor_sync(0xffffffffu, ps, 1);
            ps += __shfl_xor_sync(0xffffffffu, ps, 2);
            ps += __shfl_xor_sync(0xffffffffu, ps, 4);
            ps += __shfl_xor_sync(0xffffffffu, ps, 8);
            pd += __shfl_xor_sync(0xffffffffu, pd, 1);
            pd += __shfl_xor_sync(0xffffffffu, pd, 2);
            pd += __shfl_xor_sync(0xffffffffu, pd, 4);
            pd += __shfl_xor_sync(0xffffffffu, pd, 8);
            if ((l & 15) == 0) {
                int n = n0 + rbase + rr;
                if (n < NN) {
                    sarr[blockIdx.y * NN + n] = ps;
                    darr[blockIdx.y * NN + n] = pd;
                }
            }
        }
    }
}

// ------------------------- per-edge softmax weights (no max shift) -----------
template <int HEADS>
__global__ void k_ew(const int* __restrict__ csrc, const int* __restrict__ cdst,
                     const float* __restrict__ sarr, const float* __restrict__ darr,
                     float* __restrict__ ew) {
    int p = blockIdx.x * blockDim.x + threadIdx.x;
    if (p >= EE) return;
    int s = csrc[p], d = cdst[p];
    if (HEADS == 4) {
        float4 sv = ((const float4*)sarr)[s];
        float4 dv = ((const float4*)darr)[d];
        float4 w;
        w.x = __expf(lrelu(sv.x + dv.x));
        w.y = __expf(lrelu(sv.y + dv.y));
        w.z = __expf(lrelu(sv.z + dv.z));
        w.w = __expf(lrelu(sv.w + dv.w));
        ((float4*)ew)[p] = w;
    } else {
        float sv = sarr[s] + sarr[NN + s];
        float dv = darr[d] + darr[NN + d];
        ew[p] = __expf(lrelu(sv + dv));
    }
}

// ------------------------- edge aggregation (warp per node) ------------------
template <int HEADS>
__global__ void k_agg(const float* __restrict__ bias, float* __restrict__ out,
                      const float* __restrict__ hp, const float* __restrict__ sarr,
                      const float* __restrict__ darr, const int* __restrict__ off,
                      const int* __restrict__ csrc, const float* __restrict__ ew) {
    __shared__ float swv[8][32][HEADS];
    __shared__ int   ssrc[8][32];
    int warp = threadIdx.x >> 5, lane = threadIdx.x & 31;
    int n = blockIdx.x * 8 + warp;
    if (n >= NN) return;

    int off0 = off[n];
    int deg = off[n + 1] - off0;

    float selfw[HEADS], denp[HEADS];
    if (HEADS == 4) {
#pragma unroll
        for (int h = 0; h < 4; h++) {
            float sv = sarr[n * 4 + h];
            float dv = darr[n * 4 + h];
            selfw[h] = __expf(lrelu(sv + dv));
            denp[h] = 0.f;
        }
    } else {
        float sv = sarr[n] + sarr[NN + n];
        float dv = darr[n] + darr[NN + n];
        selfw[0] = __expf(lrelu(sv + dv));
        denp[0] = 0.f;
    }
    int myhead = (HEADS == 4) ? (lane >> 3) : 0;

    float4 acc0, acc1, acc2, acc3;
    {
        float ws = selfw[myhead];
        float4 v = ((const float4*)hp)[n * 32 + lane];
        acc0.x = ws * v.x; acc0.y = ws * v.y; acc0.z = ws * v.z; acc0.w = ws * v.w;
        acc1 = make_float4(0.f, 0.f, 0.f, 0.f);
        acc2 = make_float4(0.f, 0.f, 0.f, 0.f);
        acc3 = make_float4(0.f, 0.f, 0.f, 0.f);
    }

    for (int base = 0; base < deg; base += 32) {
        int cnt = deg - base; if (cnt > 32) cnt = 32;
        if (lane < cnt) {
            int p = off0 + base + lane;
            ssrc[warp][lane] = csrc[p];
            if (HEADS == 4) {
                float4 w = ((const float4*)ew)[p];
                swv[warp][lane][0] = w.x; denp[0] += w.x;
                swv[warp][lane][1] = w.y; denp[1] += w.y;
                swv[warp][lane][2] = w.z; denp[2] += w.z;
                swv[warp][lane][3] = w.w; denp[3] += w.w;
            } else {
                float w = ew[p];
                swv[warp][lane][0] = w; denp[0] += w;
            }
        }
        __syncwarp();
        int e = 0;
        for (; e + 8 <= cnt; e += 8) {
            int s0 = ssrc[warp][e],     s1 = ssrc[warp][e + 1];
            int s2 = ssrc[warp][e + 2], s3 = ssrc[warp][e + 3];
            int s4 = ssrc[warp][e + 4], s5 = ssrc[warp][e + 5];
            int s6 = ssrc[warp][e + 6], s7 = ssrc[warp][e + 7];
            float w0 = swv[warp][e][myhead],     w1 = swv[warp][e + 1][myhead];
            float w2 = swv[warp][e + 2][myhead], w3 = swv[warp][e + 3][myhead];
            float w4 = swv[warp][e + 4][myhead], w5 = swv[warp][e + 5][myhead];
            float w6 = swv[warp][e + 6][myhead], w7 = swv[warp][e + 7][myhead];
            float4 v0 = ((const float4*)hp)[s0 * 32 + lane];
            float4 v1 = ((const float4*)hp)[s1 * 32 + lane];
            float4 v2 = ((const float4*)hp)[s2 * 32 + lane];
            float4 v3 = ((const float4*)hp)[s3 * 32 + lane];
            float4 v4 = ((const float4*)hp)[s4 * 32 + lane];
            float4 v5 = ((const float4*)hp)[s5 * 32 + lane];
            float4 v6 = ((const float4*)hp)[s6 * 32 + lane];
            float4 v7 = ((const float4*)hp)[s7 * 32 + lane];
            acc0.x = fmaf(w0, v0.x, acc0.x); acc0.y = fmaf(w0, v0.y, acc0.y);
            acc0.z = fmaf(w0, v0.z, acc0.z); acc0.w = fmaf(w0, v0.w, acc0.w);
            acc1.x = fmaf(w1, v1.x, acc1.x); acc1.y = fmaf(w1, v1.y, acc1.y);
            acc1.z = fmaf(w1, v1.z, acc1.z); acc1.w = fmaf(w1, v1.w, acc1.w);
            acc2.x = fmaf(w2, v2.x, acc2.x); acc2.y = fmaf(w2, v2.y, acc2.y);
            acc2.z = fmaf(w2, v2.z, acc2.z); acc2.w = fmaf(w2, v2.w, acc2.w);
            acc3.x = fmaf(w3, v3.x, acc3.x); acc3.y = fmaf(w3, v3.y, acc3.y);
            acc3.z = fmaf(w3, v3.z, acc3.z); acc3.w = fmaf(w3, v3.w, acc3.w);
            acc0.x = fmaf(w4, v4.x, acc0.x); acc0.y = fmaf(w4, v4.y, acc0.y);
            acc0.z = fmaf(w4, v4.z, acc0.z); acc0.w = fmaf(w4, v4.w, acc0.w);
            acc1.x = fmaf(w5, v5.x, acc1.x); acc1.y = fmaf(w5, v5.y, acc1.y);
            acc1.z = fmaf(w5, v5.z, acc1.z); acc1.w = fmaf(w5, v5.w, acc1.w);
            acc2.x = fmaf(w6, v6.x, acc2.x); acc2.y = fmaf(w6, v6.y, acc2.y);
            acc2.z = fmaf(w6, v6.z, acc2.z); acc2.w = fmaf(w6, v6.w, acc2.w);
            acc3.x = fmaf(w7, v7.x, acc3.x); acc3.y = fmaf(w7, v7.y, acc3.y);
            acc3.z = fmaf(w7, v7.z, acc3.z); acc3.w = fmaf(w7, v7.w, acc3.w);
        }
        for (; e + 4 <= cnt; e += 4) {
            int s0 = ssrc[warp][e], s1 = ssrc[warp][e + 1];
            int s2 = ssrc[warp][e + 2], s3 = ssrc[warp][e + 3];
            float w0 = swv[warp][e][myhead], w1 = swv[warp][e + 1][myhead];
            float w2 = swv[warp][e + 2][myhead], w3 = swv[warp][e + 3][myhead];
            float4 v0 = ((const float4*)hp)[s0 * 32 + lane];
            float4 v1 = ((const float4*)hp)[s1 * 32 + lane];
            float4 v2 = ((const float4*)hp)[s2 * 32 + lane];
            float4 v3 = ((const float4*)hp)[s3 * 32 + lane];
            acc0.x = fmaf(w0, v0.x, acc0.x); acc0.y = fmaf(w0, v0.y, acc0.y);
            acc0.z = fmaf(w0, v0.z, acc0.z); acc0.w = fmaf(w0, v0.w, acc0.w);
            acc1.x = fmaf(w1, v1.x, acc1.x); acc1.y = fmaf(w1, v1.y, acc1.y);
            acc1.z = fmaf(w1, v1.z, acc1.z); acc1.w = fmaf(w1, v1.w, acc1.w);
            acc2.x = fmaf(w2, v2.x, acc2.x); acc2.y = fmaf(w2, v2.y, acc2.y);
            acc2.z = fmaf(w2, v2.z, acc2.z); acc2.w = fmaf(w2, v2.w, acc2.w);
            acc3.x = fmaf(w3, v3.x, acc3.x); acc3.y = fmaf(w3, v3.y, acc3.y);
            acc3.z = fmaf(w3, v3.z, acc3.z); acc3.w = fmaf(w3, v3.w, acc3.w);
        }
        for (; e < cnt; e++) {
            int s0 = ssrc[warp][e];
            float w0 = swv[warp][e][myhead];
            float4 v0 = ((const float4*)hp)[s0 * 32 + lane];
            acc0.x = fmaf(w0, v0.x, acc0.x); acc0.y = fmaf(w0, v0.y, acc0.y);
            acc0.z = fmaf(w0, v0.z, acc0.z); acc0.w = fmaf(w0, v0.w, acc0.w);
        }
        __syncwarp();
    }

#pragma unroll
    for (int o = 16; o; o >>= 1)
#pragma unroll
        for (int h = 0; h < HEADS; h++)
            denp[h] += __shfl_xor_sync(0xffffffffu, denp[h], o);

    float r = 1.f / (denp[myhead] + selfw[myhead] + 1e-16f);
    float4 bv = ((const float4*)bias)[lane];
    float4 o4;
    o4.x = fmaf(acc0.x + acc1.x + acc2.x + acc3.x, r, bv.x);
    o4.y = fmaf(acc0.y + acc1.y + acc2.y + acc3.y, r, bv.y);
    o4.z = fmaf(acc0.z + acc1.z + acc2.z + acc3.z, r, bv.z);
    o4.w = fmaf(acc0.w + acc1.w + acc2.w + acc3.w, r, bv.w);
    ((float4*)out)[n * 32 + lane] = o4;
}

// ------------------------- batchnorm statistics ------------------------------
__global__ void k_stats(const float* __restrict__ f, float* __restrict__ part,
                        float* __restrict__ part2) {
    int c = threadIdx.x;
    float s = 0.f, s2 = 0.f;
    for (int r = blockIdx.x; r < NN; r += 256) {
        float v = f[r * 128 + c];
        s += v;
        s2 = fmaf(v, v, s2);
    }
    part[blockIdx.x * 128 + c] = s;
    part2[blockIdx.x * 128 + c] = s2;
}

__global__ void k_bnfin(const float* __restrict__ g, const float* __restrict__ be,
                        const float* __restrict__ part, const float* __restrict__ part2,
                        float* __restrict__ scale, float* __restrict__ shift) {
    int c = threadIdx.x;
    float s = 0.f, s2 = 0.f;
    for (int i = 0; i < 256; i++) { s += part[i * 128 + c]; s2 += part2[i * 128 + c]; }
    float mu = s * (1.f / NN);
    float var = s2 * (1.f / NN) - mu * mu;
    float inv = rsqrtf(var + EPSB);
    float sc = g[c] * inv;
    scale[c] = sc;
    shift[c] = fmaf(-mu, sc, be[c]);
}

// ------------------------- classifier head (16 nodes/block) ------------------
__global__ void k_cls(const float* __restrict__ f, const float* __restrict__ scale,
                      const float* __restrict__ shift, const float* __restrict__ Wc1,
                      const float* __restrict__ bc1, const float* __restrict__ Wc2,
                      const float* __restrict__ bc2, float* __restrict__ out) {
    __shared__ float sh[16][128];
    __shared__ float Wsm[64 * 132];
    __shared__ float part[16][2];
    int t = threadIdx.x;
    int n0 = blockIdx.x * 16;

#pragma unroll
    for (int i = 0; i < 8; i++) {
        int idx = t + i * 256;
        int row = idx >> 7, col = idx & 127;
        int n = n0 + row;
        float v = 0.f;
        if (n < NN) v = fmaf(f[n * 128 + col], scale[col], shift[col]);
        sh[row][col] = v;
    }
#pragma unroll
    for (int i = 0; i < 32; i++) {
        int idx = t + i * 256;
        int j = idx >> 7, k = idx & 127;
        Wsm[j * 132 + k] = Wc1[idx];
    }
    __syncthreads();

    int j = t & 63, grp = t >> 6;
    float b1 = bc1[j];
    float a[4] = {b1, b1, b1, b1};
#pragma unroll 4
    for (int k = 0; k < 128; k += 4) {
        float4 w = *(const float4*)&Wsm[j * 132 + k];
#pragma unroll
        for (int q = 0; q < 4; q++) {
            float4 xv = *(const float4*)&sh[grp * 4 + q][k];
            a[q] = fmaf(w.x, xv.x, a[q]);
            a[q] = fmaf(w.y, xv.y, a[q]);
            a[q] = fmaf(w.z, xv.z, a[q]);
            a[q] = fmaf(w.w, xv.w, a[q]);
        }
    }
    float wc2 = Wc2[j];
#pragma unroll
    for (int q = 0; q < 4; q++) {
        float p = fmaxf(a[q], 0.f) * wc2;
#pragma unroll
        for (int o = 16; o; o >>= 1) p += __shfl_xor_sync(0xffffffffu, p, o);
        if ((t & 31) == 0) part[grp * 4 + q][(t >> 5) & 1] = p;
    }
    __syncthreads();
    if (t < 16) {
        int n = n0 + t;
        if (n < NN) out[n] = part[t][0] + part[t][1] + bc2[0];
    }
}

// ------------------------- launch -------------------------------------------
extern "C" void kernel_launch(void* const* d_in, const int* in_sizes, int n_in,
                              void* d_out, int out_size) {
    const float* x    = (const float*)d_in[0];
    const int*   ei   = (const int*)d_in[1];
    const float* Win  = (const float*)d_in[2];
    const float* bin  = (const float*)d_in[3];
    const float* W[3]  = {(const float*)d_in[4], (const float*)d_in[8], (const float*)d_in[12]};
    const float* As[3] = {(const float*)d_in[5], (const float*)d_in[9], (const float*)d_in[13]};
    const float* Ad[3] = {(const float*)d_in[6], (const float*)d_in[10], (const float*)d_in[14]};
    const float* Bb[3] = {(const float*)d_in[7], (const float*)d_in[11], (const float*)d_in[15]};
    const float* Gm[3] = {(const float*)d_in[16], (const float*)d_in[18], (const float*)d_in[20]};
    const float* Bt[3] = {(const float*)d_in[17], (const float*)d_in[19], (const float*)d_in[21]};
    const float* Wc1 = (const float*)d_in[22];
    const float* bc1 = (const float*)d_in[23];
    const float* Wc2 = (const float*)d_in[24];
    const float* bc2 = (const float*)d_in[25];
    float* out = (float*)d_out;

    float *buf0, *buf1, *hp, *sarr, *darr, *ew, *Wt, *scale, *shift, *part, *part2;
    int *deg, *cur, *off, *csrc, *cdst;
    cudaGetSymbolAddress((void**)&buf0, g_buf0);
    cudaGetSymbolAddress((void**)&buf1, g_buf1);
    cudaGetSymbolAddress((void**)&hp, g_hp);
    cudaGetSymbolAddress((void**)&sarr, g_s);
    cudaGetSymbolAddress((void**)&darr, g_d);
    cudaGetSymbolAddress((void**)&ew, g_ew);
    cudaGetSymbolAddress((void**)&Wt, g_Wt);
    cudaGetSymbolAddress((void**)&scale, g_scale);
    cudaGetSymbolAddress((void**)&shift, g_shift);
    cudaGetSymbolAddress((void**)&part, g_part);
    cudaGetSymbolAddress((void**)&part2, g_part2);
    cudaGetSymbolAddress((void**)&deg, g_deg);
    cudaGetSymbolAddress((void**)&cur, g_cur);
    cudaGetSymbolAddress((void**)&off, g_off);
    cudaGetSymbolAddress((void**)&csrc, g_csrc);
    cudaGetSymbolAddress((void**)&cdst, g_cdst);

    const int* srcv = ei;
    const int* dstv = ei + EE;

    const int GEMM_SMEM = (128 * 132 + 128 * 68) * 4;  // 102400 B -> 2 blocks/SM
    cudaFuncSetAttribute(k_gemm<4>, cudaFuncAttributeMaxDynamicSharedMemorySize, GEMM_SMEM);
    cudaFuncSetAttribute(k_gemm<1>, cudaFuncAttributeMaxDynamicSharedMemorySize, GEMM_SMEM);

    dim3 ggrid((NN + 127) / 128, 2);

    // launches 1-4 (4th = layer-0 GEMM, profiled by ncu)
    k_input<<<(NN + 1) / 2, 256>>>(x, Win, bin, buf0);
    k_t128<<<64, 256>>>(W[0], Wt);
    k_t128<<<64, 256>>>(W[1], Wt + HH * HH);
    k_gemm<4><<<ggrid, 256, GEMM_SMEM>>>(buf0, Wt, As[0], Ad[0], scale, shift, 0,
                                         hp, sarr, darr);
    k_t128<<<64, 256>>>(W[2], Wt + 2 * HH * HH);
    k_zero2<<<(NN + 255) / 256, 256>>>(deg, cur, NN);
    k_hist<<<(EE + 255) / 256, 256>>>(dstv, deg);
    k_scan<<<1, 1024>>>(deg, off);
    k_fill<<<(EE + 255) / 256, 256>>>(srcv, dstv, cur, off, csrc, cdst);

    float* bufs[2] = {buf0, buf1};
    int cur_b = 0;
    for (int L = 0; L < 3; L++) {
        float* in = bufs[cur_b];
        float* o = bufs[cur_b ^ 1];
        if (L > 0) {
            if (L < 2)
                k_gemm<4><<<ggrid, 256, GEMM_SMEM>>>(in, Wt + L * HH * HH, As[L], Ad[L],
                                                     scale, shift, 1, hp, sarr, darr);
            else
                k_gemm<1><<<ggrid, 256, GEMM_SMEM>>>(in, Wt + L * HH * HH, As[L], Ad[L],
                                                     scale, shift, 1, hp, sarr, darr);
        }
        if (L < 2) {
            k_ew<4><<<(EE + 255) / 256, 256>>>(csrc, cdst, sarr, darr, ew);
            k_agg<4><<<(NN + 7) / 8, 256>>>(Bb[L], o, hp, sarr, darr, off, csrc, ew);
        } else {
            k_ew<1><<<(EE + 255) / 256, 256>>>(csrc, cdst, sarr, darr, ew);
            k_agg<1><<<(NN + 7) / 8, 256>>>(Bb[L], o, hp, sarr, darr, off, csrc, ew);
        }
        k_stats<<<256, 128>>>(o, part, part2);
        k_bnfin<<<1, 128>>>(Gm[L], Bt[L], part, part2, scale, shift);
        cur_b ^= 1;
    }

    k_cls<<<(NN + 15) / 16, 256>>>(bufs[cur_b], scale, shift, Wc1, bc1, Wc2, bc2, out);
}

// round 7
// speedup vs baseline: 1.1485x; 1.1485x over previous
#include <cuda_runtime.h>

#define NN 50000
#define EE 800000
#define HH 128
#define NEGS 0.2f
#define EPSB 1e-5f

// ------------------------- device scratch ----------------------------------
__device__ float g_buf0[NN * HH];
__device__ float g_buf1[NN * HH];
__device__ float g_hp[NN * HH];
__device__ float g_s[NN * 4];
__device__ float g_d[NN * 4];
__device__ float g_ew[EE * 4];
__device__ float g_Wt[3 * HH * HH];
__device__ int   g_deg[NN];
__device__ int   g_cur[NN];
__device__ int   g_off[NN + 1];
__device__ int   g_csrc[EE];
__device__ int   g_cdst[EE];
__device__ float g_gs[HH];
__device__ float g_gs2[HH];
__device__ float g_scale[HH];
__device__ float g_shift[HH];

__device__ __forceinline__ float lrelu(float v) { return v > 0.f ? v : NEGS * v; }

// packed f32x2 helpers (FFMA2 — only reachable via PTX)
__device__ __forceinline__ unsigned long long pk2(float x) {
    unsigned long long r;
    asm("mov.b64 %0, {%1, %1};" : "=l"(r) : "f"(x));
    return r;
}
__device__ __forceinline__ void fma2(unsigned long long& d, unsigned long long a,
                                     unsigned long long b) {
    asm("fma.rn.f32x2 %0, %1, %2, %0;" : "+l"(d) : "l"(a), "l"(b));
}
__device__ __forceinline__ float2 up2(unsigned long long v) {
    float2 r;
    asm("mov.b64 {%0, %1}, %2;" : "=f"(r.x), "=f"(r.y) : "l"(v));
    return r;
}

// ------------------------- CSR build ----------------------------------------
__global__ void k_zero2(int* __restrict__ a, int* __restrict__ b, int n) {
    int i = blockIdx.x * blockDim.x + threadIdx.x;
    if (i < n) { a[i] = 0; b[i] = 0; }
}

__global__ void k_hist(const int* __restrict__ dst, int* __restrict__ deg) {
    int e = blockIdx.x * blockDim.x + threadIdx.x;
    if (e < EE) atomicAdd(&deg[dst[e]], 1);
}

__global__ void k_scan(const int* __restrict__ deg, int* __restrict__ off) {
    __shared__ int ssum[1024];
    int t = threadIdx.x;
    const int CH = (NN + 1023) / 1024;
    int beg = t * CH;
    int end = beg + CH; if (end > NN) end = NN;
    int s = 0;
    for (int i = beg; i < end; i++) s += deg[i];
    ssum[t] = s;
    __syncthreads();
    for (int o = 1; o < 1024; o <<= 1) {
        int v = 0;
        if (t >= o) v = ssum[t - o];
        __syncthreads();
        if (t >= o) ssum[t] += v;
        __syncthreads();
    }
    int run = (t > 0) ? ssum[t - 1] : 0;
    for (int i = beg; i < end; i++) { off[i] = run; run += deg[i]; }
    if (t == 1023) off[NN] = ssum[1023];
}

__global__ void k_fill(const int* __restrict__ src, const int* __restrict__ dst,
                       int* __restrict__ cur, const int* __restrict__ off,
                       int* __restrict__ csrc, int* __restrict__ cdst) {
    int e = blockIdx.x * blockDim.x + threadIdx.x;
    if (e < EE) {
        int d = dst[e];
        int p = off[d] + atomicAdd(&cur[d], 1);
        csrc[p] = src[e];
        cdst[p] = d;
    }
}

// ------------------------- weight transpose: Wt[k][c] = W[c][k] -------------
__global__ void k_t128(const float* __restrict__ W, float* __restrict__ Wt) {
    int idx = blockIdx.x * blockDim.x + threadIdx.x;
    if (idx < 128 * 128) {
        int c = idx >> 7, k = idx & 127;
        Wt[k * 128 + c] = W[idx];
    }
}

// ------------------------- input layer --------------------------------------
__global__ void k_input(const float* __restrict__ x, const float* __restrict__ Win,
                        const float* __restrict__ bin, float* __restrict__ out) {
    int n = blockIdx.x * 2 + (threadIdx.x >> 7);
    int c = threadIdx.x & 127;
    if (n >= NN) return;
    float a = bin[c];
#pragma unroll
    for (int k = 0; k < 5; k++) a = fmaf(x[n * 5 + k], Win[c * 5 + k], a);
    out[n * 128 + c] = fmaxf(a, 0.f);
}

// ------------------------- fused BN+relu + GEMM + attn coefficients ---------
// Round-5 design: 64 rows x 64 cols, 256 threads, 3 blocks/SM.
template <int HEADS>
__global__ void __launch_bounds__(256, 3)
k_gemm(const float* __restrict__ in, const float* __restrict__ Wt,
       const float* __restrict__ as_, const float* __restrict__ ad_,
       const float* __restrict__ scale, const float* __restrict__ shift,
       int useBN, float* __restrict__ hp,
       float* __restrict__ sarr, float* __restrict__ darr) {
    extern __shared__ float smf[];
    float* Asm = smf;              // [128k][68 rows]
    float* Wsm = smf + 128 * 68;   // [128k][68 cols]
    int t = threadIdx.x;
    int l = t & 31, w = t >> 5;
    int n0 = blockIdx.x * 64;
    int c0 = blockIdx.y * 64;

#pragma unroll
    for (int i = 0; i < 8; i++) {
        int idx4 = t + i * 256;
        int k = idx4 >> 4, cc = (idx4 & 15) * 4;
        float4 v = *(const float4*)(Wt + k * 128 + c0 + cc);
        *(float4*)(Wsm + k * 68 + cc) = v;
    }
#pragma unroll
    for (int i = 0; i < 8; i++) {
        int col = l + (i & 3) * 32;
        int rowg = w * 2 + (i >> 2);
        int nb = n0 + rowg * 4;
        float sc = 1.f, sh = 0.f;
        if (useBN) { sc = scale[col]; sh = shift[col]; }
        float4 v;
        float* vp = &v.x;
#pragma unroll
        for (int r = 0; r < 4; r++) {
            float xv = 0.f;
            if (nb + r < NN) {
                xv = in[(nb + r) * 128 + col];
                if (useBN) xv = fmaxf(fmaf(xv, sc, sh), 0.f);
            }
            vp[r] = xv;
        }
        *(float4*)(Asm + col * 68 + rowg * 4) = v;
    }
    __syncthreads();

    int rbase = w * 8 + (l >> 4) * 4;
    int cloc = (l & 15) * 4;
    const float* ap = Asm + rbase;
    const float* wp = Wsm + cloc;

    unsigned long long acc[2][4];
#pragma unroll
    for (int rp = 0; rp < 2; rp++)
#pragma unroll
        for (int c = 0; c < 4; c++) acc[rp][c] = 0ull;

#pragma unroll 4
    for (int k = 0; k < 128; k++) {
        ulonglong2 ua = *(const ulonglong2*)(ap + k * 68);
        float4 wv = *(const float4*)(wp + k * 68);
        unsigned long long pw0 = pk2(wv.x), pw1 = pk2(wv.y);
        unsigned long long pw2 = pk2(wv.z), pw3 = pk2(wv.w);
        fma2(acc[0][0], ua.x, pw0); fma2(acc[0][1], ua.x, pw1);
        fma2(acc[0][2], ua.x, pw2); fma2(acc[0][3], ua.x, pw3);
        fma2(acc[1][0], ua.y, pw0); fma2(acc[1][1], ua.y, pw1);
        fma2(acc[1][2], ua.y, pw2); fma2(acc[1][3], ua.y, pw3);
    }

    float accf[4][4];
#pragma unroll
    for (int rp = 0; rp < 2; rp++)
#pragma unroll
        for (int c = 0; c < 4; c++) {
            float2 f = up2(acc[rp][c]);
            accf[2 * rp][c] = f.x;
            accf[2 * rp + 1][c] = f.y;
        }

#pragma unroll
    for (int rr = 0; rr < 4; rr++) {
        int n = n0 + rbase + rr;
        if (n < NN)
            *(float4*)&hp[n * 128 + c0 + cloc] =
                make_float4(accf[rr][0], accf[rr][1], accf[rr][2], accf[rr][3]);
    }

    float asv[4], adv[4];
#pragma unroll
    for (int j = 0; j < 4; j++) {
        asv[j] = as_[c0 + cloc + j];
        adv[j] = ad_[c0 + cloc + j];
    }
#pragma unroll
    for (int rr = 0; rr < 4; rr++) {
        float ps = 0.f, pd = 0.f;
#pragma unroll
        for (int j = 0; j < 4; j++) {
            ps = fmaf(accf[rr][j], asv[j], ps);
            pd = fmaf(accf[rr][j], adv[j], pd);
        }
        if (HEADS == 4) {
            ps += __shfl_xor_sync(0xffffffffu, ps, 1);
            ps += __shfl_xor_sync(0xffffffffu, ps, 2);
            ps += __shfl_xor_sync(0xffffffffu, ps, 4);
            pd += __shfl_xor_sync(0xffffffffu, pd, 1);
            pd += __shfl_xor_sync(0xffffffffu, pd, 2);
            pd += __shfl_xor_sync(0xffffffffu, pd, 4);
            if ((l & 7) == 0) {
                int n = n0 + rbase + rr;
                if (n < NN) {
                    int h = blockIdx.y * 2 + ((l >> 3) & 1);
                    sarr[n * 4 + h] = ps;
                    darr[n * 4 + h] = pd;
                }
            }
        } else {
            ps += __shfl_xor_sync(0xffffffffu, ps, 1);
            ps += __shfl_xor_sync(0xffffffffu, ps, 2);
            ps += __shfl_xor_sync(0xffffffffu, ps, 4);
            ps += __shfl_xor_sync(0xffffffffu, ps, 8);
            pd += __shfl_xor_sync(0xffffffffu, pd, 1);
            pd += __shfl_xor_sync(0xffffffffu, pd, 2);
            pd += __shfl_xor_sync(0xffffffffu, pd, 4);
            pd += __shfl_xor_sync(0xffffffffu, pd, 8);
            if ((l & 15) == 0) {
                int n = n0 + rbase + rr;
                if (n < NN) {
                    sarr[blockIdx.y * NN + n] = ps;
                    darr[blockIdx.y * NN + n] = pd;
                }
            }
        }
    }
}

// ------------------------- per-edge softmax weights (no max shift) -----------
// Block 0 also zeros the BN-stat accumulators for the upcoming k_agg.
template <int HEADS>
__global__ void k_ew(const int* __restrict__ csrc, const int* __restrict__ cdst,
                     const float* __restrict__ sarr, const float* __restrict__ darr,
                     float* __restrict__ ew, float* __restrict__ gs,
                     float* __restrict__ gs2) {
    if (blockIdx.x == 0 && threadIdx.x < 128) {
        gs[threadIdx.x] = 0.f;
        gs2[threadIdx.x] = 0.f;
    }
    int p = blockIdx.x * blockDim.x + threadIdx.x;
    if (p >= EE) return;
    int s = csrc[p], d = cdst[p];
    if (HEADS == 4) {
        float4 sv = ((const float4*)sarr)[s];
        float4 dv = ((const float4*)darr)[d];
        float4 w;
        w.x = __expf(lrelu(sv.x + dv.x));
        w.y = __expf(lrelu(sv.y + dv.y));
        w.z = __expf(lrelu(sv.z + dv.z));
        w.w = __expf(lrelu(sv.w + dv.w));
        ((float4*)ew)[p] = w;
    } else {
        float sv = sarr[s] + sarr[NN + s];
        float dv = darr[d] + darr[NN + d];
        ew[p] = __expf(lrelu(sv + dv));
    }
}

// ------------------------- edge aggregation + fused BN stats -----------------
// Warp per node; grid = NN/8 = 6250 exactly (no tail).
template <int HEADS>
__global__ void k_agg(const float* __restrict__ bias, float* __restrict__ out,
                      const float* __restrict__ hp, const float* __restrict__ sarr,
                      const float* __restrict__ darr, const int* __restrict__ off,
                      const int* __restrict__ csrc, const float* __restrict__ ew,
                      float* __restrict__ gs, float* __restrict__ gs2) {
    __shared__ float swv[8][32][HEADS];
    __shared__ int   ssrc[8][32];
    __shared__ float ssum[128], ssum2[128];
    int warp = threadIdx.x >> 5, lane = threadIdx.x & 31;
    int n = blockIdx.x * 8 + warp;

    if (threadIdx.x < 128) { ssum[threadIdx.x] = 0.f; ssum2[threadIdx.x] = 0.f; }
    __syncthreads();

    int off0 = off[n];
    int deg = off[n + 1] - off0;

    float selfw[HEADS], denp[HEADS];
    if (HEADS == 4) {
#pragma unroll
        for (int h = 0; h < 4; h++) {
            float sv = sarr[n * 4 + h];
            float dv = darr[n * 4 + h];
            selfw[h] = __expf(lrelu(sv + dv));
            denp[h] = 0.f;
        }
    } else {
        float sv = sarr[n] + sarr[NN + n];
        float dv = darr[n] + darr[NN + n];
        selfw[0] = __expf(lrelu(sv + dv));
        denp[0] = 0.f;
    }
    int myhead = (HEADS == 4) ? (lane >> 3) : 0;

    float4 acc0, acc1, acc2, acc3;
    {
        float ws = selfw[myhead];
        float4 v = ((const float4*)hp)[n * 32 + lane];
        acc0.x = ws * v.x; acc0.y = ws * v.y; acc0.z = ws * v.z; acc0.w = ws * v.w;
        acc1 = make_float4(0.f, 0.f, 0.f, 0.f);
        acc2 = make_float4(0.f, 0.f, 0.f, 0.f);
        acc3 = make_float4(0.f, 0.f, 0.f, 0.f);
    }

    for (int base = 0; base < deg; base += 32) {
        int cnt = deg - base; if (cnt > 32) cnt = 32;
        if (lane < cnt) {
            int p = off0 + base + lane;
            ssrc[warp][lane] = csrc[p];
            if (HEADS == 4) {
                float4 w = ((const float4*)ew)[p];
                swv[warp][lane][0] = w.x; denp[0] += w.x;
                swv[warp][lane][1] = w.y; denp[1] += w.y;
                swv[warp][lane][2] = w.z; denp[2] += w.z;
                swv[warp][lane][3] = w.w; denp[3] += w.w;
            } else {
                float w = ew[p];
                swv[warp][lane][0] = w; denp[0] += w;
            }
        }
        __syncwarp();
        int e = 0;
        for (; e + 8 <= cnt; e += 8) {
            int s0 = ssrc[warp][e],     s1 = ssrc[warp][e + 1];
            int s2 = ssrc[warp][e + 2], s3 = ssrc[warp][e + 3];
            int s4 = ssrc[warp][e + 4], s5 = ssrc[warp][e + 5];
            int s6 = ssrc[warp][e + 6], s7 = ssrc[warp][e + 7];
            float w0 = swv[warp][e][myhead],     w1 = swv[warp][e + 1][myhead];
            float w2 = swv[warp][e + 2][myhead], w3 = swv[warp][e + 3][myhead];
            float w4 = swv[warp][e + 4][myhead], w5 = swv[warp][e + 5][myhead];
            float w6 = swv[warp][e + 6][myhead], w7 = swv[warp][e + 7][myhead];
            float4 v0 = ((const float4*)hp)[s0 * 32 + lane];
            float4 v1 = ((const float4*)hp)[s1 * 32 + lane];
            float4 v2 = ((const float4*)hp)[s2 * 32 + lane];
            float4 v3 = ((const float4*)hp)[s3 * 32 + lane];
            float4 v4 = ((const float4*)hp)[s4 * 32 + lane];
            float4 v5 = ((const float4*)hp)[s5 * 32 + lane];
            float4 v6 = ((const float4*)hp)[s6 * 32 + lane];
            float4 v7 = ((const float4*)hp)[s7 * 32 + lane];
            acc0.x = fmaf(w0, v0.x, acc0.x); acc0.y = fmaf(w0, v0.y, acc0.y);
            acc0.z = fmaf(w0, v0.z, acc0.z); acc0.w = fmaf(w0, v0.w, acc0.w);
            acc1.x = fmaf(w1, v1.x, acc1.x); acc1.y = fmaf(w1, v1.y, acc1.y);
            acc1.z = fmaf(w1, v1.z, acc1.z); acc1.w = fmaf(w1, v1.w, acc1.w);
            acc2.x = fmaf(w2, v2.x, acc2.x); acc2.y = fmaf(w2, v2.y, acc2.y);
            acc2.z = fmaf(w2, v2.z, acc2.z); acc2.w = fmaf(w2, v2.w, acc2.w);
            acc3.x = fmaf(w3, v3.x, acc3.x); acc3.y = fmaf(w3, v3.y, acc3.y);
            acc3.z = fmaf(w3, v3.z, acc3.z); acc3.w = fmaf(w3, v3.w, acc3.w);
            acc0.x = fmaf(w4, v4.x, acc0.x); acc0.y = fmaf(w4, v4.y, acc0.y);
            acc0.z = fmaf(w4, v4.z, acc0.z); acc0.w = fmaf(w4, v4.w, acc0.w);
            acc1.x = fmaf(w5, v5.x, acc1.x); acc1.y = fmaf(w5, v5.y, acc1.y);
            acc1.z = fmaf(w5, v5.z, acc1.z); acc1.w = fmaf(w5, v5.w, acc1.w);
            acc2.x = fmaf(w6, v6.x, acc2.x); acc2.y = fmaf(w6, v6.y, acc2.y);
            acc2.z = fmaf(w6, v6.z, acc2.z); acc2.w = fmaf(w6, v6.w, acc2.w);
            acc3.x = fmaf(w7, v7.x, acc3.x); acc3.y = fmaf(w7, v7.y, acc3.y);
            acc3.z = fmaf(w7, v7.z, acc3.z); acc3.w = fmaf(w7, v7.w, acc3.w);
        }
        for (; e + 4 <= cnt; e += 4) {
            int s0 = ssrc[warp][e], s1 = ssrc[warp][e + 1];
            int s2 = ssrc[warp][e + 2], s3 = ssrc[warp][e + 3];
            float w0 = swv[warp][e][myhead], w1 = swv[warp][e + 1][myhead];
            float w2 = swv[warp][e + 2][myhead], w3 = swv[warp][e + 3][myhead];
            float4 v0 = ((const float4*)hp)[s0 * 32 + lane];
            float4 v1 = ((const float4*)hp)[s1 * 32 + lane];
            float4 v2 = ((const float4*)hp)[s2 * 32 + lane];
            float4 v3 = ((const float4*)hp)[s3 * 32 + lane];
            acc0.x = fmaf(w0, v0.x, acc0.x); acc0.y = fmaf(w0, v0.y, acc0.y);
            acc0.z = fmaf(w0, v0.z, acc0.z); acc0.w = fmaf(w0, v0.w, acc0.w);
            acc1.x = fmaf(w1, v1.x, acc1.x); acc1.y = fmaf(w1, v1.y, acc1.y);
            acc1.z = fmaf(w1, v1.z, acc1.z); acc1.w = fmaf(w1, v1.w, acc1.w);
            acc2.x = fmaf(w2, v2.x, acc2.x); acc2.y = fmaf(w2, v2.y, acc2.y);
            acc2.z = fmaf(w2, v2.z, acc2.z); acc2.w = fmaf(w2, v2.w, acc2.w);
            acc3.x = fmaf(w3, v3.x, acc3.x); acc3.y = fmaf(w3, v3.y, acc3.y);
            acc3.z = fmaf(w3, v3.z, acc3.z); acc3.w = fmaf(w3, v3.w, acc3.w);
        }
        for (; e < cnt; e++) {
            int s0 = ssrc[warp][e];
            float w0 = swv[warp][e][myhead];
            float4 v0 = ((const float4*)hp)[s0 * 32 + lane];
            acc0.x = fmaf(w0, v0.x, acc0.x); acc0.y = fmaf(w0, v0.y, acc0.y);
            acc0.z = fmaf(w0, v0.z, acc0.z); acc0.w = fmaf(w0, v0.w, acc0.w);
        }
        __syncwarp();
    }

#pragma unroll
    for (int o = 16; o; o >>= 1)
#pragma unroll
        for (int h = 0; h < HEADS; h++)
            denp[h] += __shfl_xor_sync(0xffffffffu, denp[h], o);

    float r = 1.f / (denp[myhead] + selfw[myhead] + 1e-16f);
    float4 bv = ((const float4*)bias)[lane];
    float4 o4;
    o4.x = fmaf(acc0.x + acc1.x + acc2.x + acc3.x, r, bv.x);
    o4.y = fmaf(acc0.y + acc1.y + acc2.y + acc3.y, r, bv.y);
    o4.z = fmaf(acc0.z + acc1.z + acc2.z + acc3.z, r, bv.z);
    o4.w = fmaf(acc0.w + acc1.w + acc2.w + acc3.w, r, bv.w);
    ((float4*)out)[n * 32 + lane] = o4;

    // fused BN statistics: per-block smem reduction, then global atomics
    int c4 = lane * 4;
    atomicAdd(&ssum[c4 + 0], o4.x); atomicAdd(&ssum2[c4 + 0], o4.x * o4.x);
    atomicAdd(&ssum[c4 + 1], o4.y); atomicAdd(&ssum2[c4 + 1], o4.y * o4.y);
    atomicAdd(&ssum[c4 + 2], o4.z); atomicAdd(&ssum2[c4 + 2], o4.z * o4.z);
    atomicAdd(&ssum[c4 + 3], o4.w); atomicAdd(&ssum2[c4 + 3], o4.w * o4.w);
    __syncthreads();
    if (threadIdx.x < 128) {
        atomicAdd(&gs[threadIdx.x], ssum[threadIdx.x]);
        atomicAdd(&gs2[threadIdx.x], ssum2[threadIdx.x]);
    }
}

// ------------------------- batchnorm finalize --------------------------------
__global__ void k_bnfin(const float* __restrict__ g, const float* __restrict__ be,
                        const float* __restrict__ gs, const float* __restrict__ gs2,
                        float* __restrict__ scale, float* __restrict__ shift) {
    int c = threadIdx.x;
    float s = gs[c], s2 = gs2[c];
    float mu = s * (1.f / NN);
    float var = s2 * (1.f / NN) - mu * mu;
    float inv = rsqrtf(var + EPSB);
    float sc = g[c] * inv;
    scale[c] = sc;
    shift[c] = fmaf(-mu, sc, be[c]);
}

// ------------------------- classifier head (16 nodes/block) ------------------
__global__ void k_cls(const float* __restrict__ f, const float* __restrict__ scale,
                      const float* __restrict__ shift, const float* __restrict__ Wc1,
                      const float* __restrict__ bc1, const float* __restrict__ Wc2,
                      const float* __restrict__ bc2, float* __restrict__ out) {
    __shared__ float sh[16][128];
    __shared__ float Wsm[64 * 132];
    __shared__ float part[16][2];
    int t = threadIdx.x;
    int n0 = blockIdx.x * 16;

#pragma unroll
    for (int i = 0; i < 8; i++) {
        int idx = t + i * 256;
        int row = idx >> 7, col = idx & 127;
        int n = n0 + row;
        float v = 0.f;
        if (n < NN) v = fmaf(f[n * 128 + col], scale[col], shift[col]);
        sh[row][col] = v;
    }
#pragma unroll
    for (int i = 0; i < 32; i++) {
        int idx = t + i * 256;
        int j = idx >> 7, k = idx & 127;
        Wsm[j * 132 + k] = Wc1[idx];
    }
    __syncthreads();

    int j = t & 63, grp = t >> 6;
    float b1 = bc1[j];
    float a[4] = {b1, b1, b1, b1};
#pragma unroll 4
    for (int k = 0; k < 128; k += 4) {
        float4 w = *(const float4*)&Wsm[j * 132 + k];
#pragma unroll
        for (int q = 0; q < 4; q++) {
            float4 xv = *(const float4*)&sh[grp * 4 + q][k];
            a[q] = fmaf(w.x, xv.x, a[q]);
            a[q] = fmaf(w.y, xv.y, a[q]);
            a[q] = fmaf(w.z, xv.z, a[q]);
            a[q] = fmaf(w.w, xv.w, a[q]);
        }
    }
    float wc2 = Wc2[j];
#pragma unroll
    for (int q = 0; q < 4; q++) {
        float p = fmaxf(a[q], 0.f) * wc2;
#pragma unroll
        for (int o = 16; o; o >>= 1) p += __shfl_xor_sync(0xffffffffu, p, o);
        if ((t & 31) == 0) part[grp * 4 + q][(t >> 5) & 1] = p;
    }
    __syncthreads();
    if (t < 16) {
        int n = n0 + t;
        if (n < NN) out[n] = part[t][0] + part[t][1] + bc2[0];
    }
}

// ------------------------- launch -------------------------------------------
extern "C" void kernel_launch(void* const* d_in, const int* in_sizes, int n_in,
                              void* d_out, int out_size) {
    const float* x    = (const float*)d_in[0];
    const int*   ei   = (const int*)d_in[1];
    const float* Win  = (const float*)d_in[2];
    const float* bin  = (const float*)d_in[3];
    const float* W[3]  = {(const float*)d_in[4], (const float*)d_in[8], (const float*)d_in[12]};
    const float* As[3] = {(const float*)d_in[5], (const float*)d_in[9], (const float*)d_in[13]};
    const float* Ad[3] = {(const float*)d_in[6], (const float*)d_in[10], (const float*)d_in[14]};
    const float* Bb[3] = {(const float*)d_in[7], (const float*)d_in[11], (const float*)d_in[15]};
    const float* Gm[3] = {(const float*)d_in[16], (const float*)d_in[18], (const float*)d_in[20]};
    const float* Bt[3] = {(const float*)d_in[17], (const float*)d_in[19], (const float*)d_in[21]};
    const float* Wc1 = (const float*)d_in[22];
    const float* bc1 = (const float*)d_in[23];
    const float* Wc2 = (const float*)d_in[24];
    const float* bc2 = (const float*)d_in[25];
    float* out = (float*)d_out;

    float *buf0, *buf1, *hp, *sarr, *darr, *ew, *Wt, *scale, *shift, *gs, *gs2;
    int *deg, *cur, *off, *csrc, *cdst;
    cudaGetSymbolAddress((void**)&buf0, g_buf0);
    cudaGetSymbolAddress((void**)&buf1, g_buf1);
    cudaGetSymbolAddress((void**)&hp, g_hp);
    cudaGetSymbolAddress((void**)&sarr, g_s);
    cudaGetSymbolAddress((void**)&darr, g_d);
    cudaGetSymbolAddress((void**)&ew, g_ew);
    cudaGetSymbolAddress((void**)&Wt, g_Wt);
    cudaGetSymbolAddress((void**)&scale, g_scale);
    cudaGetSymbolAddress((void**)&shift, g_shift);
    cudaGetSymbolAddress((void**)&gs, g_gs);
    cudaGetSymbolAddress((void**)&gs2, g_gs2);
    cudaGetSymbolAddress((void**)&deg, g_deg);
    cudaGetSymbolAddress((void**)&cur, g_cur);
    cudaGetSymbolAddress((void**)&off, g_off);
    cudaGetSymbolAddress((void**)&csrc, g_csrc);
    cudaGetSymbolAddress((void**)&cdst, g_cdst);

    const int* srcv = ei;
    const int* dstv = ei + EE;

    const int GEMM_SMEM = 2 * 128 * 68 * 4;  // 69632 B -> 3 blocks/SM
    cudaFuncSetAttribute(k_gemm<4>, cudaFuncAttributeMaxDynamicSharedMemorySize, GEMM_SMEM);
    cudaFuncSetAttribute(k_gemm<1>, cudaFuncAttributeMaxDynamicSharedMemorySize, GEMM_SMEM);

    dim3 ggrid((NN + 63) / 64, 2);

    // launches 1-4 (4th = layer-0 GEMM, profiled by ncu)
    k_input<<<(NN + 1) / 2, 256>>>(x, Win, bin, buf0);
    k_t128<<<64, 256>>>(W[0], Wt);
    k_t128<<<64, 256>>>(W[1], Wt + HH * HH);
    k_gemm<4><<<ggrid, 256, GEMM_SMEM>>>(buf0, Wt, As[0], Ad[0], scale, shift, 0,
                                         hp, sarr, darr);
    k_t128<<<64, 256>>>(W[2], Wt + 2 * HH * HH);
    k_zero2<<<(NN + 255) / 256, 256>>>(deg, cur, NN);
    k_hist<<<(EE + 255) / 256, 256>>>(dstv, deg);
    k_scan<<<1, 1024>>>(deg, off);
    k_fill<<<(EE + 255) / 256, 256>>>(srcv, dstv, cur, off, csrc, cdst);

    float* bufs[2] = {buf0, buf1};
    int cur_b = 0;
    for (int L = 0; L < 3; L++) {
        float* in = bufs[cur_b];
        float* o = bufs[cur_b ^ 1];
        if (L > 0) {
            if (L < 2)
                k_gemm<4><<<ggrid, 256, GEMM_SMEM>>>(in, Wt + L * HH * HH, As[L], Ad[L],
                                                     scale, shift, 1, hp, sarr, darr);
            else
                k_gemm<1><<<ggrid, 256, GEMM_SMEM>>>(in, Wt + L * HH * HH, As[L], Ad[L],
                                                     scale, shift, 1, hp, sarr, darr);
        }
        if (L < 2) {
            k_ew<4><<<(EE + 255) / 256, 256>>>(csrc, cdst, sarr, darr, ew, gs, gs2);
            k_agg<4><<<NN / 8, 256>>>(Bb[L], o, hp, sarr, darr, off, csrc, ew, gs, gs2);
        } else {
            k_ew<1><<<(EE + 255) / 256, 256>>>(csrc, cdst, sarr, darr, ew, gs, gs2);
            k_agg<1><<<NN / 8, 256>>>(Bb[L], o, hp, sarr, darr, off, csrc, ew, gs, gs2);
        }
        k_bnfin<<<1, 128>>>(Gm[L], Bt[L], gs, gs2, scale, shift);
        cur_b ^= 1;
    }

    k_cls<<<(NN + 15) / 16, 256>>>(bufs[cur_b], scale, shift, Wc1, bc1, Wc2, bc2, out);
}